// round 4
// baseline (speedup 1.0000x reference)
#include <cuda_runtime.h>
#include <cuda_fp16.h>
#include <cstdint>

// Problem: B=4, S=4096, D_IN=D_OUT=512, K=8  ->  M=16384, N=512, K'=4096
#define NTOK   16384
#define DIN    512
#define DOUT   512
#define NEXP   8
#define NITER  128            // 16 i-chunks * 8 experts, BK=32
#define NSTAGE 5              // B cp.async ring depth
#define XSTR   36             // f32 per x-smem row (144B, 16B aligned)
#define BSTR   80             // bytes per B-smem row (conflict-free ldmatrix)

// ---- device scratch (no runtime allocation allowed) ----
__device__ __align__(16) __half g_wh[NEXP * DOUT * DIN];   // fp16 weights, 4 MB
__device__ __align__(16) float  g_coef[NTOK * NEXP];       // softmax coeffs

// ---- dynamic smem layout (bytes) ----
#define OFF_COEF 0                         // 128*8*4      = 4096
#define OFF_BIAS 4096                      // 8*128*4      = 4096
#define OFF_X    8192                      // 2*128*144    = 36864
#define OFF_B    45056                     // 5*128*80     = 51200
#define SMEM_TOTAL 96256

// ================= PTX helpers =================
__device__ __forceinline__ uint32_t smem_u32(const void* p) {
    uint32_t a;
    asm("{ .reg .u64 t; cvta.to.shared.u64 t, %1; cvt.u32.u64 %0, t; }" : "=r"(a) : "l"(p));
    return a;
}
__device__ __forceinline__ void cpa16(uint32_t dst, const void* src) {
    asm volatile("cp.async.cg.shared.global [%0], [%1], 16;" :: "r"(dst), "l"(src) : "memory");
}
__device__ __forceinline__ void cpa_commit() {
    asm volatile("cp.async.commit_group;" ::: "memory");
}
__device__ __forceinline__ void cpa_wait3() {
    asm volatile("cp.async.wait_group 3;" ::: "memory");
}
__device__ __forceinline__ void ldmx4(uint32_t& d0, uint32_t& d1, uint32_t& d2, uint32_t& d3,
                                      uint32_t addr) {
    asm volatile("ldmatrix.sync.aligned.m8n8.x4.shared.b16 {%0,%1,%2,%3}, [%4];"
                 : "=r"(d0), "=r"(d1), "=r"(d2), "=r"(d3) : "r"(addr));
}
__device__ __forceinline__ void mma16816(float& d0, float& d1, float& d2, float& d3,
                                         uint32_t a0, uint32_t a1, uint32_t a2, uint32_t a3,
                                         uint32_t b0, uint32_t b1) {
    asm volatile(
        "mma.sync.aligned.m16n8k16.row.col.f32.f16.f16.f32 "
        "{%0,%1,%2,%3}, {%4,%5,%6,%7}, {%8,%9}, {%0,%1,%2,%3};"
        : "+f"(d0), "+f"(d1), "+f"(d2), "+f"(d3)
        : "r"(a0), "r"(a1), "r"(a2), "r"(a3), "r"(b0), "r"(b1));
}
__device__ __forceinline__ uint32_t h2u(__half2 h) {
    return *reinterpret_cast<uint32_t*>(&h);
}
__device__ __forceinline__ uint32_t f2h2(float a, float b) {
    __half2 h = __floats2half2_rn(a, b);
    return h2u(h);
}

// ================= kernel 1: W fp32 -> fp16 =================
__global__ void __launch_bounds__(256) wconv_kernel(const float* __restrict__ w) {
    size_t i = (size_t)blockIdx.x * 256 + threadIdx.x;   // float4 idx, 524288 total
    float4 v = ((const float4*)w)[i];
    uint2 o;
    o.x = f2h2(v.x, v.y);
    o.y = f2h2(v.z, v.w);
    ((uint2*)g_wh)[i] = o;
}

// ================= kernel 2: gating softmax =================
__global__ void __launch_bounds__(256) gate_kernel(const float* __restrict__ x,
                                                   const float* __restrict__ mw,
                                                   const float* __restrict__ mb) {
    __shared__ float sw[NEXP * DIN];
    __shared__ float sbias[NEXP];
    for (int i = threadIdx.x; i < NEXP * DIN; i += 256) sw[i] = mw[i];
    if (threadIdx.x < NEXP) sbias[threadIdx.x] = mb[threadIdx.x];
    __syncthreads();

    int w = threadIdx.x >> 5, lane = threadIdx.x & 31;
    int gw = blockIdx.x * 8 + w;   // 1024 warps total
    for (int t = gw; t < NTOK; t += 1024) {
        float4 xv[4];
        const float4* xr = (const float4*)(x + (size_t)t * DIN);
#pragma unroll
        for (int j = 0; j < 4; ++j) xv[j] = xr[lane + 32 * j];
        float acc[NEXP];
#pragma unroll
        for (int k = 0; k < NEXP; ++k) {
            const float4* wr = (const float4*)(sw + k * DIN);
            float s = 0.f;
#pragma unroll
            for (int j = 0; j < 4; ++j) {
                float4 wv = wr[lane + 32 * j];
                s += xv[j].x * wv.x + xv[j].y * wv.y + xv[j].z * wv.z + xv[j].w * wv.w;
            }
            acc[k] = s;
        }
#pragma unroll
        for (int k = 0; k < NEXP; ++k)
#pragma unroll
            for (int o = 16; o; o >>= 1) acc[k] += __shfl_xor_sync(0xffffffffu, acc[k], o);
        float mx = -1e30f;
#pragma unroll
        for (int k = 0; k < NEXP; ++k) { acc[k] += sbias[k]; mx = fmaxf(mx, acc[k]); }
        float sum = 0.f;
#pragma unroll
        for (int k = 0; k < NEXP; ++k) { acc[k] = expf(acc[k] - mx); sum += acc[k]; }
        float inv = 1.f / sum;
        if (lane == 0) {
            float4* op = (float4*)(g_coef + (size_t)t * NEXP);
            op[0] = make_float4(acc[0] * inv, acc[1] * inv, acc[2] * inv, acc[3] * inv);
            op[1] = make_float4(acc[4] * inv, acc[5] * inv, acc[6] * inv, acc[7] * inv);
        }
    }
}

// ================= kernel 3: fused mixture GEMM (HMMA) =================
__global__ void __launch_bounds__(256, 1) moe_gemm_kernel(const float* __restrict__ x,
                                                          const float* __restrict__ eb,
                                                          float* __restrict__ out) {
    extern __shared__ char smem[];
    const uint32_t sb = smem_u32(smem);
    const int tid = threadIdx.x;
    const int w = tid >> 5, l = tid & 31;
    const int wm = w >> 2, wn = w & 3;           // warp grid 2(m) x 4(n), tile 64x32
    const int tbase = (blockIdx.x >> 2) * 128;   // 128 m-blocks
    const int obase = (blockIdx.x & 3) * 128;    // 4 n-blocks

    float* coefs = (float*)(smem + OFF_COEF);
    float* biass = (float*)(smem + OFF_BIAS);

    // stage coeff tile [128][8] and bias tile [8][128]
    {
        float4 v = ((const float4*)(g_coef + (size_t)tbase * NEXP))[tid];
        ((float4*)coefs)[tid] = v;
        int k = tid >> 5, c = (tid & 31) * 4;    // 8k * 32 threads * 4 cols
        float4 b = *(const float4*)(eb + (size_t)k * DOUT + obase + c);
        *(float4*)(biass + k * 128 + c) = b;
    }

    // ---- cp.async issue helpers (as lambdas over tid) ----
    auto issue_B = [&](int it) {
        int k = it & 7, ic = it >> 3, stg = it % NSTAGE;
        int row = tid >> 1;
        const char* src = (const char*)g_wh +
            (((size_t)k * DOUT + obase + row) * DIN + (size_t)ic * 32) * 2;
        uint32_t dst = sb + OFF_B + stg * (128 * BSTR) + row * BSTR;
        int j0 = (tid & 1) * 2;
        cpa16(dst + (j0 + 0) * 16, src + (j0 + 0) * 16);
        cpa16(dst + (j0 + 1) * 16, src + (j0 + 1) * 16);
    };
    auto issue_X = [&](int ic) {
        int row = tid >> 1;
        const char* src = (const char*)(x + (size_t)(tbase + row) * DIN + ic * 32);
        uint32_t dst = sb + OFF_X + (ic & 1) * (128 * XSTR * 4) + row * (XSTR * 4);
        int j0 = (tid & 1) * 4;
#pragma unroll
        for (int j = 0; j < 4; ++j) cpa16(dst + (j0 + j) * 16, src + (j0 + j) * 16);
    };

    // prologue: groups 0..3  (group j = B(j) [+ x(j/8) when j%8==0])
    issue_B(0); issue_X(0); cpa_commit();
    issue_B(1); cpa_commit();
    issue_B(2); cpa_commit();
    issue_B(3); cpa_commit();

    float acc[4][4][4];
#pragma unroll
    for (int a = 0; a < 4; ++a)
#pragma unroll
        for (int b = 0; b < 4; ++b)
#pragma unroll
            for (int c = 0; c < 4; ++c) acc[a][b][c] = 0.f;

    uint32_t xh[4][2][4];     // x fp16 fragments, cached per i-chunk
    const int r_lo = l >> 2;  // fragment row within 16-tile
    const int c_lo = 2 * (l & 3);

    for (int it = 0; it < NITER; ++it) {
        cpa_wait3();
        __syncthreads();
        const int k = it & 7, ic = it >> 3, stg = it % NSTAGE;

        if (k == 0) {   // (re)load x fragments for this i-chunk, cvt to fp16 once
            const float* xs = (const float*)(smem + OFF_X + (ic & 1) * (128 * XSTR * 4));
#pragma unroll
            for (int mt = 0; mt < 4; ++mt) {
#pragma unroll
                for (int kt = 0; kt < 2; ++kt) {
                    int r0 = wm * 64 + mt * 16 + r_lo, r1 = r0 + 8;
                    int c = kt * 16 + c_lo;
                    float2 p00 = *(const float2*)(xs + r0 * XSTR + c);
                    float2 p10 = *(const float2*)(xs + r1 * XSTR + c);
                    float2 p01 = *(const float2*)(xs + r0 * XSTR + c + 8);
                    float2 p11 = *(const float2*)(xs + r1 * XSTR + c + 8);
                    xh[mt][kt][0] = f2h2(p00.x, p00.y);
                    xh[mt][kt][1] = f2h2(p10.x, p10.y);
                    xh[mt][kt][2] = f2h2(p01.x, p01.y);
                    xh[mt][kt][3] = f2h2(p11.x, p11.y);
                }
            }
        }

        // per-expert coeff broadcast (half2) for this thread's 8 row classes
        uint32_t cfh[8];
#pragma unroll
        for (int mt = 0; mt < 4; ++mt) {
            int r0 = wm * 64 + mt * 16 + r_lo;
            float c0 = coefs[r0 * NEXP + k];
            float c1 = coefs[(r0 + 8) * NEXP + k];
            cfh[2 * mt] = f2h2(c0, c0);
            cfh[2 * mt + 1] = f2h2(c1, c1);
        }

        // B fragments via ldmatrix.x4 (80B rows -> conflict-free)
        uint32_t bf[2][4][2];
        {
            const uint32_t bst = sb + OFF_B + stg * (128 * BSTR);
            const int tix = l >> 3, rin = l & 7;
            const int nti = tix >> 1, ks = tix & 1;
#pragma unroll
            for (int kt = 0; kt < 2; ++kt)
#pragma unroll
                for (int ntp = 0; ntp < 2; ++ntp) {
                    uint32_t addr = bst +
                        (uint32_t)(wn * 32 + ntp * 16 + nti * 8 + rin) * BSTR +
                        kt * 32 + ks * 16;
                    ldmx4(bf[kt][2 * ntp][0], bf[kt][2 * ntp][1],
                          bf[kt][2 * ntp + 1][0], bf[kt][2 * ntp + 1][1], addr);
                }
        }

        // MMA: scale x frags by coeff (HMUL2) and accumulate
#pragma unroll
        for (int mt = 0; mt < 4; ++mt) {
#pragma unroll
            for (int kt = 0; kt < 2; ++kt) {
                uint32_t a0 = h2u(__hmul2(*(__half2*)&xh[mt][kt][0], *(__half2*)&cfh[2 * mt]));
                uint32_t a1 = h2u(__hmul2(*(__half2*)&xh[mt][kt][1], *(__half2*)&cfh[2 * mt + 1]));
                uint32_t a2 = h2u(__hmul2(*(__half2*)&xh[mt][kt][2], *(__half2*)&cfh[2 * mt]));
                uint32_t a3 = h2u(__hmul2(*(__half2*)&xh[mt][kt][3], *(__half2*)&cfh[2 * mt + 1]));
#pragma unroll
                for (int nt = 0; nt < 4; ++nt)
                    mma16816(acc[mt][nt][0], acc[mt][nt][1], acc[mt][nt][2], acc[mt][nt][3],
                             a0, a1, a2, a3, bf[kt][nt][0], bf[kt][nt][1]);
            }
        }

        // issue loads for it+4
        int nx = it + 4;
        if (nx < NITER) {
            issue_B(nx);
            if ((nx & 7) == 0) issue_X(nx >> 3);
        }
        cpa_commit();
    }

    // ---- epilogue: add mixed bias, store ----
#pragma unroll
    for (int mt = 0; mt < 4; ++mt) {
        int lr0 = wm * 64 + mt * 16 + r_lo, lr1 = lr0 + 8;
        float cr0[8], cr1[8];
#pragma unroll
        for (int k = 0; k < NEXP; ++k) {
            cr0[k] = coefs[lr0 * NEXP + k];
            cr1[k] = coefs[lr1 * NEXP + k];
        }
#pragma unroll
        for (int nt = 0; nt < 4; ++nt) {
            int lc = wn * 32 + nt * 8 + c_lo;
            float b00 = 0.f, b01 = 0.f, b10 = 0.f, b11 = 0.f;
#pragma unroll
            for (int k = 0; k < NEXP; ++k) {
                float bk0 = biass[k * 128 + lc], bk1 = biass[k * 128 + lc + 1];
                b00 += cr0[k] * bk0; b01 += cr0[k] * bk1;
                b10 += cr1[k] * bk0; b11 += cr1[k] * bk1;
            }
            *(float2*)(out + (size_t)(tbase + lr0) * DOUT + obase + lc) =
                make_float2(acc[mt][nt][0] + b00, acc[mt][nt][1] + b01);
            *(float2*)(out + (size_t)(tbase + lr1) * DOUT + obase + lc) =
                make_float2(acc[mt][nt][2] + b10, acc[mt][nt][3] + b11);
        }
    }
}

// ================= launch =================
extern "C" void kernel_launch(void* const* d_in, const int* in_sizes, int n_in,
                              void* d_out, int out_size) {
    (void)in_sizes; (void)n_in; (void)out_size;
    const float* x  = (const float*)d_in[0];
    const float* ew = (const float*)d_in[1];
    const float* eb = (const float*)d_in[2];
    const float* mw = (const float*)d_in[3];
    const float* mb = (const float*)d_in[4];
    float* out = (float*)d_out;

    cudaFuncSetAttribute(moe_gemm_kernel,
                         cudaFuncAttributeMaxDynamicSharedMemorySize, SMEM_TOTAL);

    wconv_kernel<<<(NEXP * DOUT * DIN) / 4 / 256, 256>>>(ew);
    gate_kernel<<<128, 256>>>(x, mw, mb);
    moe_gemm_kernel<<<(NTOK / 128) * (DOUT / 128), 256, SMEM_TOTAL>>>(x, eb, out);
}

// round 6
// speedup vs baseline: 1.0734x; 1.0734x over previous
#include <cuda_runtime.h>
#include <cuda_fp16.h>
#include <cstdint>

// Problem: B=4, S=4096, D_IN=D_OUT=512, K=8  ->  M=16384, N=512, K'=4096
#define NTOK   16384
#define DIN    512
#define DOUT   512
#define NEXP   8
#define NITER  128            // 16 i-chunks * 8 experts, BK=32
#define NBST   6              // B cp.async ring depth
#define RSTR   80             // bytes per smem row (40 halfs) - conflict-free ldmatrix
#define STGB   10240          // 128 rows * 80B per stage

// ---- device scratch (no runtime allocation allowed) ----
__device__ __align__(16) __half g_wh[NEXP * DOUT * DIN];   // fp16 weights, 4 MB
__device__ __align__(16) __half g_xh[NTOK * DIN];          // fp16 x copy, 16 MB
__device__ __align__(16) float  g_coef[NTOK * NEXP];       // softmax coeffs

// ---- dynamic smem layout (bytes) ----
#define OFF_COEF 0                       // 128*8 f32      = 4096
#define OFF_CH2  4096                    // 128*8 half2    = 4096
#define OFF_BIAS 8192                    // 8*128 f32      = 4096
#define OFF_X    12288                   // 2 stages * 10240 = 20480
#define OFF_B    32768                   // 6 stages * 10240 = 61440
#define SMEM_TOTAL 94208

// ================= PTX helpers =================
__device__ __forceinline__ uint32_t smem_u32(const void* p) {
    uint32_t a;
    asm("{ .reg .u64 t; cvta.to.shared.u64 t, %1; cvt.u32.u64 %0, t; }" : "=r"(a) : "l"(p));
    return a;
}
__device__ __forceinline__ void cpa16(uint32_t dst, const void* src) {
    asm volatile("cp.async.cg.shared.global [%0], [%1], 16;" :: "r"(dst), "l"(src) : "memory");
}
__device__ __forceinline__ void cpa_commit() {
    asm volatile("cp.async.commit_group;" ::: "memory");
}
__device__ __forceinline__ void cpa_wait2() {
    asm volatile("cp.async.wait_group 2;" ::: "memory");
}
__device__ __forceinline__ void ldmx4(uint32_t& d0, uint32_t& d1, uint32_t& d2, uint32_t& d3,
                                      uint32_t addr) {
    asm volatile("ldmatrix.sync.aligned.m8n8.x4.shared.b16 {%0,%1,%2,%3}, [%4];"
                 : "=r"(d0), "=r"(d1), "=r"(d2), "=r"(d3) : "r"(addr));
}
__device__ __forceinline__ void mma16816(float& d0, float& d1, float& d2, float& d3,
                                         uint32_t a0, uint32_t a1, uint32_t a2, uint32_t a3,
                                         uint32_t b0, uint32_t b1) {
    asm volatile(
        "mma.sync.aligned.m16n8k16.row.col.f32.f16.f16.f32 "
        "{%0,%1,%2,%3}, {%4,%5,%6,%7}, {%8,%9}, {%0,%1,%2,%3};"
        : "+f"(d0), "+f"(d1), "+f"(d2), "+f"(d3)
        : "r"(a0), "r"(a1), "r"(a2), "r"(a3), "r"(b0), "r"(b1));
}
__device__ __forceinline__ uint32_t h2u(__half2 h) {
    return *reinterpret_cast<uint32_t*>(&h);
}
__device__ __forceinline__ uint32_t f2h2(float a, float b) {
    __half2 h = __floats2half2_rn(a, b);
    return h2u(h);
}
__device__ __forceinline__ uint32_t hmul2u(uint32_t a, uint32_t b) {
    __half2 r = __hmul2(*reinterpret_cast<__half2*>(&a), *reinterpret_cast<__half2*>(&b));
    return h2u(r);
}

// ================= kernel 1: W fp32 -> fp16 =================
__global__ void __launch_bounds__(256) wconv_kernel(const float* __restrict__ w) {
    size_t i = (size_t)blockIdx.x * 256 + threadIdx.x;   // float4 idx, 524288 total
    float4 v = ((const float4*)w)[i];
    uint2 o;
    o.x = f2h2(v.x, v.y);
    o.y = f2h2(v.z, v.w);
    ((uint2*)g_wh)[i] = o;
}

// ================= kernel 2: gating softmax + x->fp16 =================
__global__ void __launch_bounds__(256) gate_kernel(const float* __restrict__ x,
                                                   const float* __restrict__ mw,
                                                   const float* __restrict__ mb) {
    __shared__ float sw[NEXP * DIN];
    __shared__ float sbias[NEXP];
    for (int i = threadIdx.x; i < NEXP * DIN; i += 256) sw[i] = mw[i];
    if (threadIdx.x < NEXP) sbias[threadIdx.x] = mb[threadIdx.x];
    __syncthreads();

    int w = threadIdx.x >> 5, lane = threadIdx.x & 31;
    int gw = blockIdx.x * 8 + w;   // 1024 warps total
    for (int t = gw; t < NTOK; t += 1024) {
        float4 xv[4];
        const float4* xr = (const float4*)(x + (size_t)t * DIN);
#pragma unroll
        for (int j = 0; j < 4; ++j) xv[j] = xr[lane + 32 * j];
        // write fp16 copy of x (same values the GEMM consumed before)
#pragma unroll
        for (int j = 0; j < 4; ++j) {
            uint2 h;
            h.x = f2h2(xv[j].x, xv[j].y);
            h.y = f2h2(xv[j].z, xv[j].w);
            *(uint2*)(g_xh + (size_t)t * DIN + 4 * (lane + 32 * j)) = h;
        }
        float acc[NEXP];
#pragma unroll
        for (int k = 0; k < NEXP; ++k) {
            const float4* wr = (const float4*)(sw + k * DIN);
            float s = 0.f;
#pragma unroll
            for (int j = 0; j < 4; ++j) {
                float4 wv = wr[lane + 32 * j];
                s += xv[j].x * wv.x + xv[j].y * wv.y + xv[j].z * wv.z + xv[j].w * wv.w;
            }
            acc[k] = s;
        }
#pragma unroll
        for (int k = 0; k < NEXP; ++k)
#pragma unroll
            for (int o = 16; o; o >>= 1) acc[k] += __shfl_xor_sync(0xffffffffu, acc[k], o);
        float mx = -1e30f;
#pragma unroll
        for (int k = 0; k < NEXP; ++k) { acc[k] += sbias[k]; mx = fmaxf(mx, acc[k]); }
        float sum = 0.f;
#pragma unroll
        for (int k = 0; k < NEXP; ++k) { acc[k] = expf(acc[k] - mx); sum += acc[k]; }
        float inv = 1.f / sum;
        if (lane == 0) {
            float4* op = (float4*)(g_coef + (size_t)t * NEXP);
            op[0] = make_float4(acc[0] * inv, acc[1] * inv, acc[2] * inv, acc[3] * inv);
            op[1] = make_float4(acc[4] * inv, acc[5] * inv, acc[6] * inv, acc[7] * inv);
        }
    }
}

// ================= kernel 3: fused mixture GEMM (HMMA) =================
__global__ void __launch_bounds__(256, 1) moe_gemm_kernel(const float* __restrict__ eb,
                                                          float* __restrict__ out) {
    extern __shared__ char smem[];
    const uint32_t sb = smem_u32(smem);
    const int tid = threadIdx.x;
    const int w = tid >> 5, l = tid & 31;
    const int wm = w >> 2, wn = w & 3;           // warp grid 2(m) x 4(n), tile 64x32
    const int tbase = (blockIdx.x >> 2) * 128;   // 128 m-blocks
    const int obase = (blockIdx.x & 3) * 128;    // 4 n-blocks

    float*    coefs = (float*)(smem + OFF_COEF);
    uint32_t* ch2   = (uint32_t*)(smem + OFF_CH2);
    float*    biass = (float*)(smem + OFF_BIAS);

    // stage coeff tile [128][8] (f32 + half2 broadcast) and bias tile [8][128]
    {
        float4 v = ((const float4*)(g_coef + (size_t)tbase * NEXP))[tid];
        ((float4*)coefs)[tid] = v;
        uint4 hv;
        hv.x = f2h2(v.x, v.x); hv.y = f2h2(v.y, v.y);
        hv.z = f2h2(v.z, v.z); hv.w = f2h2(v.w, v.w);
        ((uint4*)ch2)[tid] = hv;
        int k = tid >> 5, c = (tid & 31) * 4;
        float4 b = *(const float4*)(eb + (size_t)k * DOUT + obase + c);
        *(float4*)(biass + k * 128 + c) = b;
    }

    // ---- cp.async issue helpers ----
    auto issue_B = [&](int it) {
        int k = it & 7, ic = it >> 3, stg = it % NBST;
        int row = tid >> 1;
        const char* src = (const char*)g_wh +
            (((size_t)k * DOUT + obase + row) * DIN + (size_t)ic * 32) * 2;
        uint32_t dst = sb + OFF_B + stg * STGB + row * RSTR + (tid & 1) * 32;
        cpa16(dst, src + (tid & 1) * 32);
        cpa16(dst + 16, src + (tid & 1) * 32 + 16);
    };
    auto issue_X = [&](int ic) {
        int row = tid >> 1;
        const char* src = (const char*)(g_xh + (size_t)(tbase + row) * DIN + ic * 32);
        uint32_t dst = sb + OFF_X + (ic & 1) * STGB + row * RSTR + (tid & 1) * 32;
        cpa16(dst, src + (tid & 1) * 32);
        cpa16(dst + 16, src + (tid & 1) * 32 + 16);
    };

    // prologue: commits 0..3 hold data for iters 0..3 (X(0) rides commit 0)
    issue_B(0); issue_X(0); cpa_commit();
    issue_B(1); cpa_commit();
    issue_B(2); cpa_commit();
    issue_B(3); cpa_commit();

    float acc[4][4][4];
#pragma unroll
    for (int a = 0; a < 4; ++a)
#pragma unroll
        for (int b = 0; b < 4; ++b)
#pragma unroll
            for (int c = 0; c < 4; ++c) acc[a][b][c] = 0.f;

    uint32_t xh[4][2][4];               // A fp16 fragments, cached per i-chunk
    const int r_lo = l >> 2;            // a0/a2 row class within 16-tile
    // ldmatrix lane->address constants
    const int arow = (l & 7) + 8 * ((l >> 3) & 1);   // A: row within 16-tile
    const uint32_t acol = (uint32_t)(l >> 4) * 16;   // A: k-half select (bytes)
    const int tix = l >> 3, rin = l & 7;             // B constants (validated R4)
    const int nti = tix >> 1, ks = tix & 1;

    for (int it = 0; it < NITER; it += 2) {
        cpa_wait2();
        __syncthreads();

        const int ic = it >> 3;
        if ((it & 7) == 0) {            // A fragments for this i-chunk via ldmatrix
            const uint32_t xa = sb + OFF_X + (ic & 1) * STGB;
#pragma unroll
            for (int mt = 0; mt < 4; ++mt)
#pragma unroll
                for (int kt = 0; kt < 2; ++kt) {
                    uint32_t addr = xa + (uint32_t)(wm * 64 + mt * 16 + arow) * RSTR +
                                    kt * 32 + acol;
                    ldmx4(xh[mt][kt][0], xh[mt][kt][1], xh[mt][kt][2], xh[mt][kt][3], addr);
                }
        }

        // front-load all shared loads for both iters of the pair
        uint32_t bf[2][2][4][2], cfh[2][8];
#pragma unroll
        for (int s = 0; s < 2; ++s) {
            const int k = (it + s) & 7, stg = (it + s) % NBST;
#pragma unroll
            for (int mt = 0; mt < 4; ++mt) {
                int r0 = wm * 64 + mt * 16 + r_lo;
                cfh[s][2 * mt]     = ch2[r0 * NEXP + k];
                cfh[s][2 * mt + 1] = ch2[(r0 + 8) * NEXP + k];
            }
            const uint32_t bst = sb + OFF_B + stg * STGB;
#pragma unroll
            for (int kt = 0; kt < 2; ++kt)
#pragma unroll
                for (int ntp = 0; ntp < 2; ++ntp) {
                    uint32_t addr = bst +
                        (uint32_t)(wn * 32 + ntp * 16 + nti * 8 + rin) * RSTR +
                        kt * 32 + ks * 16;
                    ldmx4(bf[s][kt][2 * ntp][0], bf[s][kt][2 * ntp][1],
                          bf[s][kt][2 * ntp + 1][0], bf[s][kt][2 * ntp + 1][1], addr);
                }
        }

        // issue loads for it+4 / it+5 (one commit per iter keeps group math fixed)
#pragma unroll
        for (int s = 0; s < 2; ++s) {
            int nx = it + 4 + s;
            if (nx < NITER) {
                issue_B(nx);
                if ((nx & 7) == 0) issue_X(nx >> 3);
            }
            cpa_commit();
        }

        // dense HMMA stream: 64 mma per warp per pair
#pragma unroll
        for (int s = 0; s < 2; ++s)
#pragma unroll
            for (int mt = 0; mt < 4; ++mt)
#pragma unroll
                for (int kt = 0; kt < 2; ++kt) {
                    uint32_t a0 = hmul2u(xh[mt][kt][0], cfh[s][2 * mt]);
                    uint32_t a1 = hmul2u(xh[mt][kt][1], cfh[s][2 * mt + 1]);
                    uint32_t a2 = hmul2u(xh[mt][kt][2], cfh[s][2 * mt]);
                    uint32_t a3 = hmul2u(xh[mt][kt][3], cfh[s][2 * mt + 1]);
#pragma unroll
                    for (int nt = 0; nt < 4; ++nt)
                        mma16816(acc[mt][nt][0], acc[mt][nt][1],
                                 acc[mt][nt][2], acc[mt][nt][3],
                                 a0, a1, a2, a3,
                                 bf[s][kt][nt][0], bf[s][kt][nt][1]);
                }
    }

    // ---- epilogue: add mixed bias, store ----
    const int c_lo = 2 * (l & 3);
#pragma unroll
    for (int mt = 0; mt < 4; ++mt) {
        int lr0 = wm * 64 + mt * 16 + r_lo, lr1 = lr0 + 8;
        float cr0[8], cr1[8];
#pragma unroll
        for (int k = 0; k < NEXP; ++k) {
            cr0[k] = coefs[lr0 * NEXP + k];
            cr1[k] = coefs[lr1 * NEXP + k];
        }
#pragma unroll
        for (int nt = 0; nt < 4; ++nt) {
            int lc = wn * 32 + nt * 8 + c_lo;
            float b00 = 0.f, b01 = 0.f, b10 = 0.f, b11 = 0.f;
#pragma unroll
            for (int k = 0; k < NEXP; ++k) {
                float bk0 = biass[k * 128 + lc], bk1 = biass[k * 128 + lc + 1];
                b00 += cr0[k] * bk0; b01 += cr0[k] * bk1;
                b10 += cr1[k] * bk0; b11 += cr1[k] * bk1;
            }
            *(float2*)(out + (size_t)(tbase + lr0) * DOUT + obase + lc) =
                make_float2(acc[mt][nt][0] + b00, acc[mt][nt][1] + b01);
            *(float2*)(out + (size_t)(tbase + lr1) * DOUT + obase + lc) =
                make_float2(acc[mt][nt][2] + b10, acc[mt][nt][3] + b11);
        }
    }
}

// ================= launch =================
extern "C" void kernel_launch(void* const* d_in, const int* in_sizes, int n_in,
                              void* d_out, int out_size) {
    (void)in_sizes; (void)n_in; (void)out_size;
    const float* x  = (const float*)d_in[0];
    const float* ew = (const float*)d_in[1];
    const float* eb = (const float*)d_in[2];
    const float* mw = (const float*)d_in[3];
    const float* mb = (const float*)d_in[4];
    float* out = (float*)d_out;

    cudaFuncSetAttribute(moe_gemm_kernel,
                         cudaFuncAttributeMaxDynamicSharedMemorySize, SMEM_TOTAL);

    wconv_kernel<<<(NEXP * DOUT * DIN) / 4 / 256, 256>>>(ew);
    gate_kernel<<<128, 256>>>(x, mw, mb);
    moe_gemm_kernel<<<(NTOK / 128) * (DOUT / 128), 256, SMEM_TOTAL>>>(eb, out);
}

// round 7
// speedup vs baseline: 1.5140x; 1.4105x over previous
#include <cuda_runtime.h>
#include <cuda_fp16.h>
#include <cstdint>

// Problem: B=4, S=4096, D_IN=D_OUT=512, K=8  ->  M=16384, N=512, K'=4096
#define NTOK   16384
#define DIN    512
#define DOUT   512
#define NEXP   8
#define NITER  128            // 16 i-chunks * 8 experts, BK=32
#define NBST   6              // B cp.async ring depth
#define RSTR   80             // bytes per smem row (40 halfs) - conflict-free ldmatrix
#define XSTGB  10240          // X stage: 128 rows * 80B
#define BSTGB  5120           // B stage:  64 rows * 80B

// ---- device scratch (no runtime allocation allowed) ----
__device__ __align__(16) __half g_wh[NEXP * DOUT * DIN];   // fp16 weights, 4 MB
__device__ __align__(16) __half g_xh[NTOK * DIN];          // fp16 x copy, 16 MB
__device__ __align__(16) float  g_coef[NTOK * NEXP];       // softmax coeffs

// ---- dynamic smem layout (bytes) ----
#define OFF_COEF 0                       // 128*8 f32   = 4096
#define OFF_CH2  4096                    // 128*8 half2 = 4096
#define OFF_BIAS 8192                    // 8*64 f32    = 2048
#define OFF_X    10240                   // 2 stages * 10240 = 20480
#define OFF_B    30720                   // 6 stages * 5120  = 30720
#define SMEM_TOTAL 61440

// ================= PTX helpers =================
__device__ __forceinline__ uint32_t smem_u32(const void* p) {
    uint32_t a;
    asm("{ .reg .u64 t; cvta.to.shared.u64 t, %1; cvt.u32.u64 %0, t; }" : "=r"(a) : "l"(p));
    return a;
}
__device__ __forceinline__ void cpa16(uint32_t dst, const void* src) {
    asm volatile("cp.async.cg.shared.global [%0], [%1], 16;" :: "r"(dst), "l"(src) : "memory");
}
__device__ __forceinline__ void cpa_commit() {
    asm volatile("cp.async.commit_group;" ::: "memory");
}
__device__ __forceinline__ void cpa_wait2() {
    asm volatile("cp.async.wait_group 2;" ::: "memory");
}
__device__ __forceinline__ void ldmx4(uint32_t& d0, uint32_t& d1, uint32_t& d2, uint32_t& d3,
                                      uint32_t addr) {
    asm volatile("ldmatrix.sync.aligned.m8n8.x4.shared.b16 {%0,%1,%2,%3}, [%4];"
                 : "=r"(d0), "=r"(d1), "=r"(d2), "=r"(d3) : "r"(addr));
}
__device__ __forceinline__ void mma16816(float& d0, float& d1, float& d2, float& d3,
                                         uint32_t a0, uint32_t a1, uint32_t a2, uint32_t a3,
                                         uint32_t b0, uint32_t b1) {
    asm volatile(
        "mma.sync.aligned.m16n8k16.row.col.f32.f16.f16.f32 "
        "{%0,%1,%2,%3}, {%4,%5,%6,%7}, {%8,%9}, {%0,%1,%2,%3};"
        : "+f"(d0), "+f"(d1), "+f"(d2), "+f"(d3)
        : "r"(a0), "r"(a1), "r"(a2), "r"(a3), "r"(b0), "r"(b1));
}
__device__ __forceinline__ uint32_t h2u(__half2 h) {
    return *reinterpret_cast<uint32_t*>(&h);
}
__device__ __forceinline__ uint32_t f2h2(float a, float b) {
    __half2 h = __floats2half2_rn(a, b);
    return h2u(h);
}
__device__ __forceinline__ uint32_t hmul2u(uint32_t a, uint32_t b) {
    __half2 r = __hmul2(*reinterpret_cast<__half2*>(&a), *reinterpret_cast<__half2*>(&b));
    return h2u(r);
}

// ================= kernel 1: W fp32 -> fp16 =================
__global__ void __launch_bounds__(256) wconv_kernel(const float* __restrict__ w) {
    size_t i = (size_t)blockIdx.x * 256 + threadIdx.x;   // float4 idx, 524288 total
    float4 v = ((const float4*)w)[i];
    uint2 o;
    o.x = f2h2(v.x, v.y);
    o.y = f2h2(v.z, v.w);
    ((uint2*)g_wh)[i] = o;
}

// ================= kernel 2: gating softmax + x->fp16 =================
__global__ void __launch_bounds__(256) gate_kernel(const float* __restrict__ x,
                                                   const float* __restrict__ mw,
                                                   const float* __restrict__ mb) {
    __shared__ float sw[NEXP * DIN];
    __shared__ float sbias[NEXP];
    for (int i = threadIdx.x; i < NEXP * DIN; i += 256) sw[i] = mw[i];
    if (threadIdx.x < NEXP) sbias[threadIdx.x] = mb[threadIdx.x];
    __syncthreads();

    int w = threadIdx.x >> 5, lane = threadIdx.x & 31;
    int gw = blockIdx.x * 8 + w;   // 1024 warps total
    for (int t = gw; t < NTOK; t += 1024) {
        float4 xv[4];
        const float4* xr = (const float4*)(x + (size_t)t * DIN);
#pragma unroll
        for (int j = 0; j < 4; ++j) xv[j] = xr[lane + 32 * j];
        // write fp16 copy of x (same values the GEMM consumes)
#pragma unroll
        for (int j = 0; j < 4; ++j) {
            uint2 h;
            h.x = f2h2(xv[j].x, xv[j].y);
            h.y = f2h2(xv[j].z, xv[j].w);
            *(uint2*)(g_xh + (size_t)t * DIN + 4 * (lane + 32 * j)) = h;
        }
        float acc[NEXP];
#pragma unroll
        for (int k = 0; k < NEXP; ++k) {
            const float4* wr = (const float4*)(sw + k * DIN);
            float s = 0.f;
#pragma unroll
            for (int j = 0; j < 4; ++j) {
                float4 wv = wr[lane + 32 * j];
                s += xv[j].x * wv.x + xv[j].y * wv.y + xv[j].z * wv.z + xv[j].w * wv.w;
            }
            acc[k] = s;
        }
#pragma unroll
        for (int k = 0; k < NEXP; ++k)
#pragma unroll
            for (int o = 16; o; o >>= 1) acc[k] += __shfl_xor_sync(0xffffffffu, acc[k], o);
        float mx = -1e30f;
#pragma unroll
        for (int k = 0; k < NEXP; ++k) { acc[k] += sbias[k]; mx = fmaxf(mx, acc[k]); }
        float sum = 0.f;
#pragma unroll
        for (int k = 0; k < NEXP; ++k) { acc[k] = expf(acc[k] - mx); sum += acc[k]; }
        float inv = 1.f / sum;
        if (lane == 0) {
            float4* op = (float4*)(g_coef + (size_t)t * NEXP);
            op[0] = make_float4(acc[0] * inv, acc[1] * inv, acc[2] * inv, acc[3] * inv);
            op[1] = make_float4(acc[4] * inv, acc[5] * inv, acc[6] * inv, acc[7] * inv);
        }
    }
}

// ================= kernel 3: fused mixture GEMM (HMMA) =================
// CTA: 128 threads, tile 128(m) x 64(n); warp grid 2m x 2n, warp tile 64x32.
// Grid 1024 = 128 m-blocks * 8 n-blocks; 2 CTAs/SM.
__global__ void __launch_bounds__(128, 2) moe_gemm_kernel(const float* __restrict__ eb,
                                                          float* __restrict__ out) {
    extern __shared__ char smem[];
    const uint32_t sb = smem_u32(smem);
    const int tid = threadIdx.x;
    const int w = tid >> 5, l = tid & 31;
    const int wm = w >> 1, wn = w & 1;           // warp grid 2(m) x 2(n)
    const int tbase = (blockIdx.x >> 3) * 128;   // 128 m-blocks
    const int obase = (blockIdx.x & 7) * 64;     // 8 n-blocks

    float*    coefs = (float*)(smem + OFF_COEF);
    uint32_t* ch2   = (uint32_t*)(smem + OFF_CH2);
    float*    biass = (float*)(smem + OFF_BIAS);

    // stage coeff tile [128][8] (f32 + half2 broadcast) and bias tile [8][64]
#pragma unroll
    for (int r = 0; r < 2; ++r) {
        int i = tid + r * 128;                   // 256 float4 rows of coeffs
        float4 v = ((const float4*)(g_coef + (size_t)tbase * NEXP))[i];
        ((float4*)coefs)[i] = v;
        uint4 hv;
        hv.x = f2h2(v.x, v.x); hv.y = f2h2(v.y, v.y);
        hv.z = f2h2(v.z, v.z); hv.w = f2h2(v.w, v.w);
        ((uint4*)ch2)[i] = hv;
    }
    {
        int k = tid >> 4, c = (tid & 15) * 4;    // 8k * 16 threads * 4 cols
        float4 b = *(const float4*)(eb + (size_t)k * DOUT + obase + c);
        *(float4*)(biass + k * 64 + c) = b;
    }

    // ---- cp.async issue helpers ----
    auto issue_B = [&](int it) {
        int k = it & 7, ic = it >> 3, stg = it % NBST;
        int row = tid >> 1;                      // 64 rows, 2 threads/row
        const char* src = (const char*)g_wh +
            (((size_t)k * DOUT + obase + row) * DIN + (size_t)ic * 32) * 2;
        uint32_t dst = sb + OFF_B + stg * BSTGB + row * RSTR + (tid & 1) * 32;
        cpa16(dst, src + (tid & 1) * 32);
        cpa16(dst + 16, src + (tid & 1) * 32 + 16);
    };
    auto issue_X = [&](int ic) {
        int row = tid;                           // 128 rows, 1 thread/row (64B)
        const char* src = (const char*)(g_xh + (size_t)(tbase + row) * DIN + ic * 32);
        uint32_t dst = sb + OFF_X + (ic & 1) * XSTGB + row * RSTR;
#pragma unroll
        for (int j = 0; j < 4; ++j) cpa16(dst + j * 16, src + j * 16);
    };

    // prologue: commits 0..3 hold data for iters 0..3 (X(0) rides commit 0)
    issue_B(0); issue_X(0); cpa_commit();
    issue_B(1); cpa_commit();
    issue_B(2); cpa_commit();
    issue_B(3); cpa_commit();

    float acc[4][4][4];
#pragma unroll
    for (int a = 0; a < 4; ++a)
#pragma unroll
        for (int b = 0; b < 4; ++b)
#pragma unroll
            for (int c = 0; c < 4; ++c) acc[a][b][c] = 0.f;

    uint32_t xh[4][2][4];               // A fp16 fragments, cached per i-chunk
    const int r_lo = l >> 2;            // a0/a2 row class within 16-tile
    // ldmatrix lane->address constants
    const int arow = (l & 7) + 8 * ((l >> 3) & 1);   // A: row within 16-tile
    const uint32_t acol = (uint32_t)(l >> 4) * 16;   // A: k-half select (bytes)
    const int tix = l >> 3, rin = l & 7;             // B constants (validated R4)
    const int nti = tix >> 1, ks = tix & 1;

    for (int it = 0; it < NITER; it += 2) {
        cpa_wait2();
        __syncthreads();

        const int ic = it >> 3;
        if ((it & 7) == 0) {            // A fragments for this i-chunk via ldmatrix
            const uint32_t xa = sb + OFF_X + (ic & 1) * XSTGB;
#pragma unroll
            for (int mt = 0; mt < 4; ++mt)
#pragma unroll
                for (int kt = 0; kt < 2; ++kt) {
                    uint32_t addr = xa + (uint32_t)(wm * 64 + mt * 16 + arow) * RSTR +
                                    kt * 32 + acol;
                    ldmx4(xh[mt][kt][0], xh[mt][kt][1], xh[mt][kt][2], xh[mt][kt][3], addr);
                }
        }

        // front-load all shared loads for both iters of the pair
        uint32_t bf[2][2][4][2], cfh[2][8];
#pragma unroll
        for (int s = 0; s < 2; ++s) {
            const int k = (it + s) & 7, stg = (it + s) % NBST;
#pragma unroll
            for (int mt = 0; mt < 4; ++mt) {
                int r0 = wm * 64 + mt * 16 + r_lo;
                cfh[s][2 * mt]     = ch2[r0 * NEXP + k];
                cfh[s][2 * mt + 1] = ch2[(r0 + 8) * NEXP + k];
            }
            const uint32_t bst = sb + OFF_B + stg * BSTGB;
#pragma unroll
            for (int kt = 0; kt < 2; ++kt)
#pragma unroll
                for (int ntp = 0; ntp < 2; ++ntp) {
                    uint32_t addr = bst +
                        (uint32_t)(wn * 32 + ntp * 16 + nti * 8 + rin) * RSTR +
                        kt * 32 + ks * 16;
                    ldmx4(bf[s][kt][2 * ntp][0], bf[s][kt][2 * ntp][1],
                          bf[s][kt][2 * ntp + 1][0], bf[s][kt][2 * ntp + 1][1], addr);
                }
        }

        // issue loads for it+4 / it+5 (one commit per iter keeps group math fixed)
#pragma unroll
        for (int s = 0; s < 2; ++s) {
            int nx = it + 4 + s;
            if (nx < NITER) {
                issue_B(nx);
                if ((nx & 7) == 0) issue_X(nx >> 3);
            }
            cpa_commit();
        }

        // dense HMMA stream: 64 mma per warp per pair
#pragma unroll
        for (int s = 0; s < 2; ++s)
#pragma unroll
            for (int mt = 0; mt < 4; ++mt)
#pragma unroll
                for (int kt = 0; kt < 2; ++kt) {
                    uint32_t a0 = hmul2u(xh[mt][kt][0], cfh[s][2 * mt]);
                    uint32_t a1 = hmul2u(xh[mt][kt][1], cfh[s][2 * mt + 1]);
                    uint32_t a2 = hmul2u(xh[mt][kt][2], cfh[s][2 * mt]);
                    uint32_t a3 = hmul2u(xh[mt][kt][3], cfh[s][2 * mt + 1]);
#pragma unroll
                    for (int nt = 0; nt < 4; ++nt)
                        mma16816(acc[mt][nt][0], acc[mt][nt][1],
                                 acc[mt][nt][2], acc[mt][nt][3],
                                 a0, a1, a2, a3,
                                 bf[s][kt][nt][0], bf[s][kt][nt][1]);
                }
    }

    // ---- epilogue: add mixed bias, store ----
    const int c_lo = 2 * (l & 3);
#pragma unroll
    for (int mt = 0; mt < 4; ++mt) {
        int lr0 = wm * 64 + mt * 16 + r_lo, lr1 = lr0 + 8;
        float cr0[8], cr1[8];
#pragma unroll
        for (int k = 0; k < NEXP; ++k) {
            cr0[k] = coefs[lr0 * NEXP + k];
            cr1[k] = coefs[lr1 * NEXP + k];
        }
#pragma unroll
        for (int nt = 0; nt < 4; ++nt) {
            int lc = wn * 32 + nt * 8 + c_lo;
            float b00 = 0.f, b01 = 0.f, b10 = 0.f, b11 = 0.f;
#pragma unroll
            for (int k = 0; k < NEXP; ++k) {
                float bk0 = biass[k * 64 + lc], bk1 = biass[k * 64 + lc + 1];
                b00 += cr0[k] * bk0; b01 += cr0[k] * bk1;
                b10 += cr1[k] * bk0; b11 += cr1[k] * bk1;
            }
            *(float2*)(out + (size_t)(tbase + lr0) * DOUT + obase + lc) =
                make_float2(acc[mt][nt][0] + b00, acc[mt][nt][1] + b01);
            *(float2*)(out + (size_t)(tbase + lr1) * DOUT + obase + lc) =
                make_float2(acc[mt][nt][2] + b10, acc[mt][nt][3] + b11);
        }
    }
}

// ================= launch =================
extern "C" void kernel_launch(void* const* d_in, const int* in_sizes, int n_in,
                              void* d_out, int out_size) {
    (void)in_sizes; (void)n_in; (void)out_size;
    const float* x  = (const float*)d_in[0];
    const float* ew = (const float*)d_in[1];
    const float* eb = (const float*)d_in[2];
    const float* mw = (const float*)d_in[3];
    const float* mb = (const float*)d_in[4];
    float* out = (float*)d_out;

    cudaFuncSetAttribute(moe_gemm_kernel,
                         cudaFuncAttributeMaxDynamicSharedMemorySize, SMEM_TOTAL);

    wconv_kernel<<<(NEXP * DOUT * DIN) / 4 / 256, 256>>>(ew);
    gate_kernel<<<128, 256>>>(x, mw, mb);
    moe_gemm_kernel<<<(NTOK / 128) * (DOUT / 64), 128, SMEM_TOTAL>>>(eb, out);
}